// round 7
// baseline (speedup 1.0000x reference)
#include <cuda_runtime.h>
#include <cuda_fp16.h>
#include <cstdint>

// Problem dims (fixed by the dataset)
#define T_ 4096
#define B_ 8
#define D_ 256
#define P_ 256
#define O_ 256
#define SCALING 0.0625f   // P^-0.5 = 1/16
#define QT 64             // q rows per flash CTA
#define KT2 256           // kv per flash tile
#define NT2 (T_ / KT2)    // 16

// Scratch (device globals: allocation-free per harness rules)
__device__ __half g_q[(size_t)B_ * T_ * P_];       // [B,T,P] scaled q (fp16)
__device__ __half g_k[(size_t)B_ * T_ * P_];       // [B,T,P]
__device__ __half g_v[(size_t)B_ * T_ * P_];       // [B,T,P]
__device__ __half g_wkqvT[(size_t)3 * P_ * D_];    // [3P, D]
__device__ __half g_woutT[(size_t)O_ * P_];        // [O, P]

// ---------------------------------------------------------------------------
__device__ __forceinline__ uint32_t f22h(float a, float b) {
    __half2 h = __floats2half2_rn(a, b);
    return *(uint32_t*)&h;
}
__device__ __forceinline__ void mma16(float* c, const uint32_t* a, uint32_t b0, uint32_t b1) {
    asm volatile(
        "mma.sync.aligned.m16n8k16.row.col.f32.f16.f16.f32 "
        "{%0,%1,%2,%3}, {%4,%5,%6,%7}, {%8,%9}, {%0,%1,%2,%3};"
        : "+f"(c[0]), "+f"(c[1]), "+f"(c[2]), "+f"(c[3])
        : "r"(a[0]), "r"(a[1]), "r"(a[2]), "r"(a[3]), "r"(b0), "r"(b1));
}
__device__ __forceinline__ void ldm4(uint32_t* r, uint32_t addr) {
    asm volatile("ldmatrix.sync.aligned.m8n8.x4.shared.b16 {%0,%1,%2,%3}, [%4];"
                 : "=r"(r[0]), "=r"(r[1]), "=r"(r[2]), "=r"(r[3]) : "r"(addr));
}
__device__ __forceinline__ void ldm4t(uint32_t* r, uint32_t addr) {
    asm volatile("ldmatrix.sync.aligned.m8n8.x4.trans.shared.b16 {%0,%1,%2,%3}, [%4];"
                 : "=r"(r[0]), "=r"(r[1]), "=r"(r[2]), "=r"(r[3]) : "r"(addr));
}
__device__ __forceinline__ uint32_t smem_u32(const void* p) {
    uint32_t a;
    asm("{ .reg .u64 t; cvta.to.shared.u64 t, %1; cvt.u32.u64 %0, t; }" : "=r"(a) : "l"(p));
    return a;
}
// ldmatrix.x4 address in a [rows][64 fp16] SW128-swizzled tile (non-trans: row-major operand)
__device__ __forceinline__ uint32_t ldm_addr(uint32_t tile, int rbase, int kk, int lane) {
    int row = rbase + (lane & 15);
    int c16 = kk * 2 + (lane >> 4);
    return tile + row * 128 + (uint32_t)((c16 * 16) ^ ((row & 7) * 16));
}
// ldmatrix.x4.trans address: operand stored [k][n] row-major, want n-major frags
__device__ __forceinline__ uint32_t ldmt_addr(uint32_t tile, int kbase, int nbase, int lane) {
    int k = kbase + (lane & 7) + 8 * ((lane >> 3) & 1);
    int n = nbase + 8 * (lane >> 4);
    return tile + k * 128 + (uint32_t)((((n >> 3) * 16) ^ ((k & 7) * 16)));
}
__device__ __forceinline__ void cpa16(uint32_t dst, const void* src) {
    asm volatile("cp.async.cg.shared.global [%0], [%1], 16;" :: "r"(dst), "l"(src));
}
#define CP_COMMIT() asm volatile("cp.async.commit_group;" ::: "memory")
#define CP_WAIT1()  asm volatile("cp.async.wait_group 1;" ::: "memory")
#define CP_WAIT0()  asm volatile("cp.async.wait_group 0;" ::: "memory")

// ---------------------------------------------------------------------------
// fp16 mma GEMM (QKV projection): CTA 128x128, K-chunk 64, double-buffered.
// A fp32 [M,K] (converted on the fly), B fp16 [N,K] K-major.
// Epilogue: bias add, q-scaling, fp16 scatter to g_q/g_k/g_v [B,T,P].
// ---------------------------------------------------------------------------
#define SMG_BYTES 65536

__global__ void __launch_bounds__(256)
gemm_qkv(const float* __restrict__ A, const __half* __restrict__ Bm,
         const float* __restrict__ bias)
{
    extern __shared__ char smem[];
    const uint32_t sb = smem_u32(smem);
    const int tid = threadIdx.x;
    const int w = tid >> 5, lane = tid & 31;
    const int wm = w & 3, wn = w >> 2;
    const int lane4 = lane >> 2, lanek = lane & 3;
    const int m0 = blockIdx.y * 128, n0 = blockIdx.x * 128;

    A  += (long)m0 * D_;
    Bm += (long)n0 * D_;

    float acc[16][4];
#pragma unroll
    for (int i = 0; i < 16; i++)
#pragma unroll
        for (int j = 0; j < 4; j++) acc[i][j] = 0.f;

    float4 pa[8], pb[4];
#pragma unroll
    for (int i = 0; i < 4; i++) {
        int f = tid + i * 256, r = f >> 3, c16 = f & 7;
        pa[2*i]   = *(const float4*)(A + (long)r * D_ + c16 * 8);
        pa[2*i+1] = *(const float4*)(A + (long)r * D_ + c16 * 8 + 4);
        pb[i]     = *(const float4*)(Bm + (long)r * D_ + c16 * 8);
    }

    for (int c = 0; c < 4; ++c) {
        const int s = c & 1;
        const uint32_t aS = sb + s * 16384;
        const uint32_t bS = sb + 32768 + s * 16384;
#pragma unroll
        for (int i = 0; i < 4; i++) {
            int f = tid + i * 256, r = f >> 3, c16 = f & 7;
            uint32_t off = (uint32_t)(r * 128 + ((c16 * 16) ^ ((r & 7) * 16)));
            uint32_t h0 = f22h(pa[2*i].x,   pa[2*i].y);
            uint32_t h1 = f22h(pa[2*i].z,   pa[2*i].w);
            uint32_t h2 = f22h(pa[2*i+1].x, pa[2*i+1].y);
            uint32_t h3 = f22h(pa[2*i+1].z, pa[2*i+1].w);
            asm volatile("st.shared.v4.b32 [%0], {%1,%2,%3,%4};"
                         :: "r"(aS + off), "r"(h0), "r"(h1), "r"(h2), "r"(h3));
            const uint32_t* pbu = (const uint32_t*)&pb[i];
            asm volatile("st.shared.v4.b32 [%0], {%1,%2,%3,%4};"
                         :: "r"(bS + off), "r"(pbu[0]), "r"(pbu[1]), "r"(pbu[2]), "r"(pbu[3]));
        }
        __syncthreads();
        if (c + 1 < 4) {
            const float*  Ag = A  + (c + 1) * 64;
            const __half* Bg = Bm + (c + 1) * 64;
#pragma unroll
            for (int i = 0; i < 4; i++) {
                int f = tid + i * 256, r = f >> 3, c16 = f & 7;
                pa[2*i]   = *(const float4*)(Ag + (long)r * D_ + c16 * 8);
                pa[2*i+1] = *(const float4*)(Ag + (long)r * D_ + c16 * 8 + 4);
                pb[i]     = *(const float4*)(Bg + (long)r * D_ + c16 * 8);
            }
        }
#pragma unroll
        for (int kk = 0; kk < 4; ++kk) {
            uint32_t af[2][4], bf[4][4];
#pragma unroll
            for (int mt = 0; mt < 2; ++mt)
                ldm4(af[mt], ldm_addr(aS, wm * 32 + mt * 16, kk, lane));
#pragma unroll
            for (int nb = 0; nb < 4; ++nb)
                ldm4(bf[nb], ldm_addr(bS, wn * 64 + nb * 16, kk, lane));
#pragma unroll
            for (int mt = 0; mt < 2; ++mt)
#pragma unroll
                for (int n8 = 0; n8 < 8; ++n8)
                    mma16(acc[mt * 8 + n8], af[mt],
                          bf[n8 >> 1][n8 & 1], bf[n8 >> 1][2 + (n8 & 1)]);
        }
        __syncthreads();
    }

    const int rb = m0 + wm * 32 + lane4;
    const int cb = n0 + wn * 64 + 2 * lanek;
#pragma unroll
    for (int mt = 0; mt < 2; ++mt) {
        const int r = rb + mt * 16;
#pragma unroll
        for (int n8 = 0; n8 < 8; ++n8) {
            float* a4 = acc[mt * 8 + n8];
            const int gc = cb + n8 * 8;
            const int seg = gc >> 8, col = gc & 255;
            float2 bv = *(const float2*)(bias + gc);
            const float scl = (seg == 0) ? SCALING : 1.0f;
            __half* dstb = (seg == 0 ? g_q : (seg == 1 ? g_k : g_v));
            int t0 = r >> 3, b0 = r & 7;
            *(uint32_t*)(dstb + ((long)b0 * T_ + t0) * P_ + col) =
                f22h((a4[0] + bv.x) * scl, (a4[1] + bv.y) * scl);
            int t1 = (r + 8) >> 3, b1 = (r + 8) & 7;
            *(uint32_t*)(dstb + ((long)b1 * T_ + t1) * P_ + col) =
                f22h((a4[2] + bv.x) * scl, (a4[3] + bv.y) * scl);
        }
    }
}

// ---------------------------------------------------------------------------
// 32x32 tiled transpose fp32 -> fp16 (weights only)
// ---------------------------------------------------------------------------
__global__ void __launch_bounds__(256)
transpose_w(const float* __restrict__ src, __half* __restrict__ dst, int R, int C)
{
    __shared__ float tile[32][33];
    const int c0 = blockIdx.x * 32, r0 = blockIdx.y * 32;
    const int x = threadIdx.x, y = threadIdx.y;
#pragma unroll
    for (int i = 0; i < 32; i += 8)
        tile[y + i][x] = src[(long)(r0 + y + i) * C + c0 + x];
    __syncthreads();
#pragma unroll
    for (int i = 0; i < 32; i += 8)
        dst[(long)(c0 + y + i) * R + r0 + x] = (__half)tile[x][y + i];
}

// ---------------------------------------------------------------------------
// Flash attention fp16 + fused output projection. 512 threads, kv tiles 256.
// smem: Q 32K (4x[64][64]) | K 2x32K ([256kv][64d], reused for W_out chunks)
//       | V 2x32K ([64kv][256d] as 4 sub-tiles) | P 32K (4x[64][64], reused
//       for fp16 O) | stats.
// ---------------------------------------------------------------------------
#define SM_Q    0
#define SM_K    32768
#define SM_V    (SM_K + 2 * 32768)
#define SM_P    (SM_V + 2 * 32768)
#define SM_ST   (SM_P + 32768)
#define SMF_BYTES (SM_ST + 5120)

__global__ void __launch_bounds__(512, 1)
flash_attn(const float* __restrict__ b_out, float* __restrict__ out)
{
    extern __shared__ char smem[];
    const uint32_t sb = smem_u32(smem);
    const int tid = threadIdx.x;
    const int w = tid >> 5, lane = tid & 31;
    const int wm = w & 1, wn = w >> 1;      // wn 0..7
    const int lane4 = lane >> 2, lanek = lane & 3;
    const int bz = blockIdx.y;
    const int t0 = blockIdx.x * QT;

    const __half* qb = g_q + ((long)bz * T_ + t0) * P_;
    const __half* kb = g_k + (long)bz * T_ * P_;
    const __half* vb = g_v + (long)bz * T_ * P_;

    float* pmax  = (float*)(smem + SM_ST);
    float* psum  = (float*)(smem + SM_ST + 2048);
    float* m_st  = (float*)(smem + SM_ST + 4096);
    float* l_st  = (float*)(smem + SM_ST + 4352);
    float* sc_st = (float*)(smem + SM_ST + 4608);

    // ---- Q resident: 4 d-chunks of [64][64] fp16, SW128 swizzle
#pragma unroll
    for (int i = 0; i < 4; i++) {
        int f = tid + i * 512;
        int r = f >> 5, c32 = f & 31;
        int kc = c32 >> 3, c16 = c32 & 7;
        float4 v = *(const float4*)(qb + (long)r * P_ + c32 * 8);
        uint32_t off = (uint32_t)(kc * 8192 + r * 128 + ((c16 * 16) ^ ((r & 7) * 16)));
        *(float4*)(smem + SM_Q + off) = v;
    }
    if (tid < QT) { m_st[tid] = -3.4e38f; l_st[tid] = 0.f; }

    float acco[2][4][4];
#pragma unroll
    for (int mt = 0; mt < 2; mt++)
#pragma unroll
        for (int nt = 0; nt < 4; nt++)
#pragma unroll
            for (int e = 0; e < 4; e++) acco[mt][nt][e] = 0.f;

    // prologue: K tile0 d-chunks 0,1 into kbuf 0,1  ([256kv][64d] each)
#pragma unroll
    for (int pc = 0; pc < 2; pc++) {
#pragma unroll
        for (int i = 0; i < 4; i++) {
            int f = tid + i * 512, r = f >> 3, c16 = f & 7;
            uint32_t dst = sb + SM_K + pc * 32768 +
                           (uint32_t)(r * 128 + ((c16 * 16) ^ ((r & 7) * 16)));
            cpa16(dst, kb + (long)r * P_ + pc * 64 + c16 * 8);
        }
        CP_COMMIT();
    }

    for (int j = 0; j < NT2; ++j) {
        // ============== S phase: S[64x256] = Q @ Kj^T  (4 d-chunks) ========
        float accs[2][4][4];
#pragma unroll
        for (int mt = 0; mt < 2; mt++)
#pragma unroll
            for (int nt = 0; nt < 4; nt++)
#pragma unroll
                for (int e = 0; e < 4; e++) accs[mt][nt][e] = 0.f;

        for (int c = 0; c < 4; ++c) {
            CP_WAIT1();
            __syncthreads();
            const uint32_t aT = sb + SM_Q + c * 8192;
            const uint32_t bT = sb + SM_K + (c & 1) * 32768;
#pragma unroll
            for (int kk = 0; kk < 4; ++kk) {
                uint32_t af[2][4], bf[2][4];
#pragma unroll
                for (int mt = 0; mt < 2; ++mt)
                    ldm4(af[mt], ldm_addr(aT, wm * 32 + mt * 16, kk, lane));
#pragma unroll
                for (int nb = 0; nb < 2; ++nb)
                    ldm4(bf[nb], ldm_addr(bT, wn * 32 + nb * 16, kk, lane));
#pragma unroll
                for (int mt = 0; mt < 2; ++mt)
#pragma unroll
                    for (int n8 = 0; n8 < 4; ++n8)
                        mma16(accs[mt][n8], af[mt],
                              bf[n8 >> 1][n8 & 1], bf[n8 >> 1][2 + (n8 & 1)]);
            }
            __syncthreads();
            if (c < 2) {
                // K d-chunk c+2 of this tile -> kbuf (c&1)
#pragma unroll
                for (int i = 0; i < 4; i++) {
                    int f = tid + i * 512, r = f >> 3, c16 = f & 7;
                    uint32_t dst = sb + SM_K + (c & 1) * 32768 +
                                   (uint32_t)(r * 128 + ((c16 * 16) ^ ((r & 7) * 16)));
                    cpa16(dst, kb + (long)(j * KT2 + r) * P_ + (c + 2) * 64 + c16 * 8);
                }
            } else {
                // V kv-chunk c-2 ([64kv][256d]) -> vbuf (c-2)
                const int vc = c - 2;
#pragma unroll
                for (int i = 0; i < 4; i++) {
                    int f = tid + i * 512, r = f >> 5, c32 = f & 31;
                    uint32_t dst = sb + SM_V + vc * 32768 +
                                   (uint32_t)((c32 >> 3) * 8192 + r * 128 +
                                              (((c32 & 7) * 16) ^ ((r & 7) * 16)));
                    cpa16(dst, vb + (long)(j * KT2 + vc * 64 + r) * P_ + c32 * 8);
                }
            }
            CP_COMMIT();
        }

        // ============== online softmax over 256 kv cols ====================
#pragma unroll
        for (int mt = 0; mt < 2; mt++) {
#pragma unroll
            for (int h = 0; h < 2; h++) {
                float mx = -3.4e38f;
#pragma unroll
                for (int nt = 0; nt < 4; nt++)
                    mx = fmaxf(mx, fmaxf(accs[mt][nt][2 * h], accs[mt][nt][2 * h + 1]));
                mx = fmaxf(mx, __shfl_xor_sync(0xffffffffu, mx, 1));
                mx = fmaxf(mx, __shfl_xor_sync(0xffffffffu, mx, 2));
                if (lanek == 0)
                    pmax[wn * 64 + wm * 32 + mt * 16 + lane4 + 8 * h] = mx;
            }
        }
        __syncthreads();
        if (tid < QT) {
            float mo = m_st[tid];
            float mn = mo;
#pragma unroll
            for (int g = 0; g < 8; g++) mn = fmaxf(mn, pmax[g * 64 + tid]);
            m_st[tid] = mn;
            sc_st[tid] = __expf(mo - mn);
        }
        __syncthreads();

#pragma unroll
        for (int mt = 0; mt < 2; mt++) {
#pragma unroll
            for (int h = 0; h < 2; h++) {
                const int r = wm * 32 + mt * 16 + lane4 + 8 * h;
                const float m = m_st[r];
                float s = 0.f;
#pragma unroll
                for (int nt = 0; nt < 4; nt++) {
                    float e0 = __expf(accs[mt][nt][2 * h] - m);
                    float e1 = __expf(accs[mt][nt][2 * h + 1] - m);
                    s += e0 + e1;
                    const int cg = wn * 32 + nt * 8 + 2 * lanek;  // kv col 0..255
                    const int kc = cg >> 6, cw = cg & 63;
                    uint32_t off = (uint32_t)(kc * 8192 + r * 128 +
                                   (((cw >> 3) * 16) ^ ((r & 7) * 16)) + (cw & 7) * 2);
                    *(uint32_t*)(smem + SM_P + off) = f22h(e0, e1);
                }
                s += __shfl_xor_sync(0xffffffffu, s, 1);
                s += __shfl_xor_sync(0xffffffffu, s, 2);
                if (lanek == 0) psum[wn * 64 + r] = s;
                const float scl = sc_st[r];
#pragma unroll
                for (int nt = 0; nt < 4; nt++) {
                    acco[mt][nt][2 * h]     *= scl;
                    acco[mt][nt][2 * h + 1] *= scl;
                }
            }
        }
        __syncthreads();
        if (tid < QT) {
            float s = 0.f;
#pragma unroll
            for (int g = 0; g < 8; g++) s += psum[g * 64 + tid];
            l_st[tid] = l_st[tid] * sc_st[tid] + s;
        }

        // ============== PV phase: O += P @ Vj  (4 kv-chunks of 64) =========
        const bool lastj = (j == NT2 - 1);
        const __half* nxt = lastj ? g_woutT : (kb + (long)((j + 1) * KT2) * P_);
        for (int d = 0; d < 4; ++d) {
            CP_WAIT1();
            __syncthreads();
            const uint32_t aT = sb + SM_P + d * 8192;       // P kv-sub-tile d
            const uint32_t bT = sb + SM_V + (d & 1) * 32768; // V chunk [64kv][256d]
#pragma unroll
            for (int kk = 0; kk < 4; ++kk) {
                uint32_t af[2][4], bt[2][4];
#pragma unroll
                for (int mt = 0; mt < 2; ++mt)
                    ldm4(af[mt], ldm_addr(aT, wm * 32 + mt * 16, kk, lane));
#pragma unroll
                for (int nb = 0; nb < 2; ++nb) {
                    const int oc = wn * 32 + nb * 16;       // output-d col
                    ldm4t(bt[nb], ldmt_addr(bT + (oc >> 6) * 8192, kk * 16, oc & 63, lane));
                }
#pragma unroll
                for (int mt = 0; mt < 2; ++mt)
#pragma unroll
                    for (int n8 = 0; n8 < 4; ++n8)
                        mma16(acco[mt][n8], af[mt],
                              bt[n8 >> 1][2 * (n8 & 1)], bt[n8 >> 1][2 * (n8 & 1) + 1]);
            }
            __syncthreads();
            if (d < 2) {
                // V kv-chunk d+2 -> vbuf (d&1)
#pragma unroll
                for (int i = 0; i < 4; i++) {
                    int f = tid + i * 512, r = f >> 5, c32 = f & 31;
                    uint32_t dst = sb + SM_V + (d & 1) * 32768 +
                                   (uint32_t)((c32 >> 3) * 8192 + r * 128 +
                                              (((c32 & 7) * 16) ^ ((r & 7) * 16)));
                    cpa16(dst, vb + (long)(j * KT2 + (d + 2) * 64 + r) * P_ + c32 * 8);
                }
            } else {
                // next [256][64] K-major chunk: next tile's K, or W_out chunks 0/1
#pragma unroll
                for (int i = 0; i < 4; i++) {
                    int f = tid + i * 512, r = f >> 3, c16 = f & 7;
                    uint32_t dst = sb + SM_K + (d - 2) * 32768 +
                                   (uint32_t)(r * 128 + ((c16 * 16) ^ ((r & 7) * 16)));
                    cpa16(dst, nxt + (long)r * P_ + (d - 2) * 64 + c16 * 8);
                }
            }
            CP_COMMIT();
        }
    }

    // ====================== fused output projection ========================
    // 1) normalize O, convert fp16, store into P region as 4 p-sub-tiles
#pragma unroll
    for (int mt = 0; mt < 2; mt++) {
#pragma unroll
        for (int h = 0; h < 2; h++) {
            const int r = wm * 32 + mt * 16 + lane4 + 8 * h;
            const float inv = 1.0f / l_st[r];
#pragma unroll
            for (int nt = 0; nt < 4; nt++) {
                const int cg = wn * 32 + nt * 8 + 2 * lanek;   // p col 0..255
                const int kc = cg >> 6, cw = cg & 63;
                uint32_t off = (uint32_t)(kc * 8192 + r * 128 +
                               (((cw >> 3) * 16) ^ ((r & 7) * 16)) + (cw & 7) * 2);
                *(uint32_t*)(smem + SM_P + off) =
                    f22h(acco[mt][nt][2 * h] * inv, acco[mt][nt][2 * h + 1] * inv);
            }
        }
    }

    // 2) out[64,256] = O @ W_outT^T ; W chunks [256o][64p] through K bufs
    float accf[2][4][4];
#pragma unroll
    for (int mt = 0; mt < 2; mt++)
#pragma unroll
        for (int nt = 0; nt < 4; nt++)
#pragma unroll
            for (int e = 0; e < 4; e++) accf[mt][nt][e] = 0.f;

    for (int g = 0; g < 4; ++g) {
        if (g < 3) CP_WAIT1(); else CP_WAIT0();
        __syncthreads();
        const uint32_t aT = sb + SM_P + g * 8192;
        const uint32_t bT = sb + SM_K + (g & 1) * 32768;
#pragma unroll
        for (int kk = 0; kk < 4; ++kk) {
            uint32_t af[2][4], bf[2][4];
#pragma unroll
            for (int mt = 0; mt < 2; ++mt)
                ldm4(af[mt], ldm_addr(aT, wm * 32 + mt * 16, kk, lane));
#pragma unroll
            for (int nb = 0; nb < 2; ++nb)
                ldm4(bf[nb], ldm_addr(bT, wn * 32 + nb * 16, kk, lane));
#pragma unroll
            for (int mt = 0; mt < 2; ++mt)
#pragma unroll
                for (int n8 = 0; n8 < 4; ++n8)
                    mma16(accf[mt][n8], af[mt],
                          bf[n8 >> 1][n8 & 1], bf[n8 >> 1][2 + (n8 & 1)]);
        }
        if (g < 2) {
            __syncthreads();
            // W chunk g+2 -> kbuf (g&1)
#pragma unroll
            for (int i = 0; i < 4; i++) {
                int f = tid + i * 512, r = f >> 3, c16 = f & 7;
                uint32_t dst = sb + SM_K + (g & 1) * 32768 +
                               (uint32_t)(r * 128 + ((c16 * 16) ^ ((r & 7) * 16)));
                cpa16(dst, g_woutT + (long)r * P_ + (g + 2) * 64 + c16 * 8);
            }
            CP_COMMIT();
        }
    }

    // 3) bias + final store to out [T,B,O] fp32
#pragma unroll
    for (int mt = 0; mt < 2; mt++) {
#pragma unroll
        for (int h = 0; h < 2; h++) {
            const int r = wm * 32 + mt * 16 + lane4 + 8 * h;
            const long base = ((long)(t0 + r) * B_ + bz) * O_;
#pragma unroll
            for (int nt = 0; nt < 4; nt++) {
                const int oc = wn * 32 + nt * 8 + 2 * lanek;
                float2 bv = *(const float2*)(b_out + oc);
                *(float2*)(out + base + oc) =
                    make_float2(accf[mt][nt][2 * h] + bv.x,
                                accf[mt][nt][2 * h + 1] + bv.y);
            }
        }
    }
}

// ---------------------------------------------------------------------------
extern "C" void kernel_launch(void* const* d_in, const int* in_sizes, int n_in,
                              void* d_out, int out_size)
{
    const float* query = (const float*)d_in[0];   // [T,B,D]
    const float* W_kqv = (const float*)d_in[1];   // [D, 3P]
    const float* b_kqv = (const float*)d_in[2];   // [3P]
    const float* W_out = (const float*)d_in[3];   // [P, O]
    const float* b_out = (const float*)d_in[4];   // [O]
    float* out = (float*)d_out;                   // [T,B,O]

    __half *wkqvT, *woutT;
    cudaGetSymbolAddress((void**)&wkqvT, g_wkqvT);
    cudaGetSymbolAddress((void**)&woutT, g_woutT);

    cudaFuncSetAttribute(gemm_qkv, cudaFuncAttributeMaxDynamicSharedMemorySize, SMG_BYTES);
    cudaFuncSetAttribute(flash_attn, cudaFuncAttributeMaxDynamicSharedMemorySize, SMF_BYTES);

    const dim3 tb(32, 8);

    // 0) weights -> [N,K] K-major fp16
    transpose_w<<<dim3(3 * P_ / 32, D_ / 32), tb>>>(W_kqv, wkqvT, D_, 3 * P_);
    transpose_w<<<dim3(O_ / 32, P_ / 32), tb>>>(W_out, woutT, P_, O_);

    // 1) QKV projection + split/scale -> g_q/g_k/g_v fp16
    gemm_qkv<<<dim3(6, 256), 256, SMG_BYTES>>>(query, wkqvT, b_kqv);

    // 2) fused flash attention + output projection -> out
    flash_attn<<<dim3(T_ / QT, B_), 512, SMF_BYTES>>>(b_out, out);
}